// round 11
// baseline (speedup 1.0000x reference)
#include <cuda_runtime.h>
#include <cuda_bf16.h>
#include <cstdint>
#include <cfloat>

#define K_DIM 4096
#define M_DIM 4096
#define NTOK_MAX 8192

// ---------------- scratch (device globals; no allocation allowed) ----------------
__device__ __align__(256) char g_Xq[(size_t)NTOK_MAX * K_DIM]; // int8 Xq (zp-offset included)
__device__ __align__(256) char g_Wq[(size_t)M_DIM * K_DIM];    // int8 Wq
__device__ float g_cs[NTOK_MAX];   // per-token act scale
__device__ float g_zp[NTOK_MAX];   // per-token zero point (integer-valued)
__device__ float g_rs[M_DIM];      // per-row weight scale
__device__ int   g_ws[M_DIM];      // per-row sum of Wq (int)

// ---------------- helpers ----------------
__device__ __forceinline__ uint32_t smem_u32(const void* p) {
    uint32_t a;
    asm("{ .reg .u64 t; cvta.to.shared.u64 t, %1; cvt.u32.u64 %0, t; }" : "=r"(a) : "l"(p));
    return a;
}
#define CP16(sm, gm) \
    asm volatile("cp.async.cg.shared.global [%0], [%1], 16;" :: "r"(sm), "l"(gm) : "memory")
#define CP_COMMIT() asm volatile("cp.async.commit_group;" ::: "memory")
#define CP_WAIT1()  asm volatile("cp.async.wait_group 1;" ::: "memory")
#define CP_WAIT0()  asm volatile("cp.async.wait_group 0;" ::: "memory")

__device__ __forceinline__ void ldsm4(uint32_t& r0, uint32_t& r1, uint32_t& r2, uint32_t& r3,
                                      uint32_t addr) {
    asm volatile("ldmatrix.sync.aligned.m8n8.x4.shared.b16 {%0,%1,%2,%3}, [%4];"
                 : "=r"(r0), "=r"(r1), "=r"(r2), "=r"(r3) : "r"(addr));
}
#define MMA_S8(d, a, b0, b1) \
    asm volatile("mma.sync.aligned.m16n8k32.row.col.s32.s8.s8.s32 " \
                 "{%0,%1,%2,%3}, {%4,%5,%6,%7}, {%8,%9}, {%0,%1,%2,%3};" \
                 : "+r"((d)[0]), "+r"((d)[1]), "+r"((d)[2]), "+r"((d)[3]) \
                 : "r"((a)[0]), "r"((a)[1]), "r"((a)[2]), "r"((a)[3]), "r"(b0), "r"(b1))

// ---------------- fused quantization: one row per 256-thread block ----------------
// Blocks [0, M_DIM): weight rows (symmetric int8 + row sum).
// Blocks [M_DIM, M_DIM + n_tok): activation tokens (asymmetric int8).
// Single pass over data: values cached in 4 x float4 registers per thread.
__global__ __launch_bounds__(256) void quant_kernel(const float* __restrict__ W,
                                                    const float* __restrict__ X) {
    const int t = threadIdx.x;
    __shared__ float sr0[8], sr1[8];
    __shared__ int sqs[8];
    __shared__ float s_scale, s_zp;

    if (blockIdx.x < M_DIM) {
        // ---- weight row: symmetric ----
        const int m = blockIdx.x;
        const float4* row = reinterpret_cast<const float4*>(W + (size_t)m * K_DIM);
        float4 v[4];
        float amax = 0.f;
#pragma unroll
        for (int i = 0; i < 4; i++) {
            v[i] = row[t + i * 256];
            amax = fmaxf(amax, fmaxf(fmaxf(fabsf(v[i].x), fabsf(v[i].y)),
                                     fmaxf(fabsf(v[i].z), fabsf(v[i].w))));
        }
#pragma unroll
        for (int o = 16; o; o >>= 1) amax = fmaxf(amax, __shfl_xor_sync(0xFFFFFFFFu, amax, o));
        if ((t & 31) == 0) sr0[t >> 5] = amax;
        __syncthreads();
        if (t == 0) {
            float a = sr0[0];
#pragma unroll
            for (int i = 1; i < 8; i++) a = fmaxf(a, sr0[i]);
            float sc = (a > 0.f) ? __fdiv_rn(a, 127.f) : 1.f;
            s_scale = sc;
            g_rs[m] = sc;
        }
        __syncthreads();
        const float sc = s_scale;
        uint32_t* o = reinterpret_cast<uint32_t*>(g_Wq + (size_t)m * K_DIM);
        int qsum = 0;
#pragma unroll
        for (int i = 0; i < 4; i++) {
            int i0 = (int)fminf(fmaxf(rintf(__fdiv_rn(v[i].x, sc)), -128.f), 127.f);
            int i1 = (int)fminf(fmaxf(rintf(__fdiv_rn(v[i].y, sc)), -128.f), 127.f);
            int i2 = (int)fminf(fmaxf(rintf(__fdiv_rn(v[i].z, sc)), -128.f), 127.f);
            int i3 = (int)fminf(fmaxf(rintf(__fdiv_rn(v[i].w, sc)), -128.f), 127.f);
            qsum += i0 + i1 + i2 + i3;
            o[t + i * 256] = (uint32_t)(i0 & 255) | ((uint32_t)(i1 & 255) << 8) |
                             ((uint32_t)(i2 & 255) << 16) | ((uint32_t)(i3 & 255) << 24);
        }
#pragma unroll
        for (int ofs = 16; ofs; ofs >>= 1) qsum += __shfl_xor_sync(0xFFFFFFFFu, qsum, ofs);
        if ((t & 31) == 0) sqs[t >> 5] = qsum;
        __syncthreads();
        if (t == 0) {
            int s = 0;
#pragma unroll
            for (int i = 0; i < 8; i++) s += sqs[i];
            g_ws[m] = s;
        }
    } else {
        // ---- activation token: asymmetric ----
        const int n = blockIdx.x - M_DIM;
        const float4* row = reinterpret_cast<const float4*>(X + (size_t)n * K_DIM);
        float4 v[4];
        float mn = FLT_MAX, mx = -FLT_MAX;
#pragma unroll
        for (int i = 0; i < 4; i++) {
            v[i] = row[t + i * 256];
            mn = fminf(mn, fminf(fminf(v[i].x, v[i].y), fminf(v[i].z, v[i].w)));
            mx = fmaxf(mx, fmaxf(fmaxf(v[i].x, v[i].y), fmaxf(v[i].z, v[i].w)));
        }
#pragma unroll
        for (int o = 16; o; o >>= 1) {
            mn = fminf(mn, __shfl_xor_sync(0xFFFFFFFFu, mn, o));
            mx = fmaxf(mx, __shfl_xor_sync(0xFFFFFFFFu, mx, o));
        }
        if ((t & 31) == 0) { sr0[t >> 5] = mn; sr1[t >> 5] = mx; }
        __syncthreads();
        if (t == 0) {
            float lo = sr0[0], hi = sr1[0];
#pragma unroll
            for (int i = 1; i < 8; i++) {
                lo = fminf(lo, sr0[i]);
                hi = fmaxf(hi, sr1[i]);
            }
            float rng = hi - lo;
            float sc = (rng > 0.f) ? __fdiv_rn(rng, 255.f) : 1.f;
            float zp = fminf(fmaxf(rintf(-128.f - __fdiv_rn(lo, sc)), -128.f), 127.f);
            s_scale = sc; s_zp = zp;
            g_cs[n] = sc;
            g_zp[n] = zp;
        }
        __syncthreads();
        const float sc = s_scale, zp = s_zp;
        uint32_t* o = reinterpret_cast<uint32_t*>(g_Xq + (size_t)n * K_DIM);
#pragma unroll
        for (int i = 0; i < 4; i++) {
            int i0 = (int)(fminf(fmaxf(rintf(__fdiv_rn(v[i].x, sc) + zp), -128.f), 127.f));
            int i1 = (int)(fminf(fmaxf(rintf(__fdiv_rn(v[i].y, sc) + zp), -128.f), 127.f));
            int i2 = (int)(fminf(fmaxf(rintf(__fdiv_rn(v[i].z, sc) + zp), -128.f), 127.f));
            int i3 = (int)(fminf(fmaxf(rintf(__fdiv_rn(v[i].w, sc) + zp), -128.f), 127.f));
            o[t + i * 256] = (uint32_t)(i0 & 255) | ((uint32_t)(i1 & 255) << 8) |
                             ((uint32_t)(i2 & 255) << 16) | ((uint32_t)(i3 & 255) << 24);
        }
    }
}

// ---------------- int8 IMMA GEMM ----------------
// CTA tile: 128 tokens x 128 features, BK = 64 B, 6-stage cp.async ring,
// 2 chunks per iteration -> ONE wait + ONE __syncthreads per chunk pair.
// 8 warps in 2x4; warp tile 64x32. 2 CTAs/SM (smem ~101KB, regs <=128).
#define BM 128
#define BN 128
#define BK 64
#define NSTAGE 6
#define NCHUNK (K_DIM / BK)                // 64
#define NPAIR (NCHUNK / 2)                 // 32
#define STAGE_BYTES ((BM + BN) * BK)       // 16384
#define CTRL_OFF (NSTAGE * STAGE_BYTES)    // 98304
#define GEMM_SMEM (CTRL_OFF + 2560)        // 100864

// swizzled offset of a 16B slot within a [rows x 64B] tile
__device__ __forceinline__ uint32_t swz(int row, int slot) {
    return (uint32_t)(row * 64 + ((slot ^ ((row >> 1) & 3)) << 4));
}

__global__ void __launch_bounds__(256, 2) gemm_kernel(const float* __restrict__ bias,
                                                      float* __restrict__ out) {
    extern __shared__ char smem[];
    uint32_t sm = smem_u32(smem);
    const int tid = threadIdx.x;
    const int wid = tid >> 5, lid = tid & 31;
    const int warpRow = wid >> 2, warpCol = wid & 3;       // 2 x 4 warps
    const int outTile = blockIdx.x;                        // 32 tiles of 128 features
    const int tokTile = blockIdx.y;                        // 64 tiles of 128 tokens
    const int tok0 = tokTile * BM, out0 = outTile * BN;

    // ---- ctrl smem (epilogue constants) ----
    float* s_cs  = (float*)(smem + CTRL_OFF);          // 128 floats
    int*   s_zpi = (int*)(smem + CTRL_OFF + 512);      // 128 ints
    float* s_rs  = (float*)(smem + CTRL_OFF + 1024);   // 128 floats
    int*   s_wsi = (int*)(smem + CTRL_OFF + 1536);     // 128 ints
    float* s_b   = (float*)(smem + CTRL_OFF + 2048);   // 128 floats
    if (tid < 128) {
        s_cs[tid]  = g_cs[tok0 + tid];
        s_zpi[tid] = (int)g_zp[tok0 + tid];
        s_rs[tid]  = g_rs[out0 + tid];
        s_wsi[tid] = g_ws[out0 + tid];
        s_b[tid]   = bias[out0 + tid];
    }

    // ---- loader per-thread invariants ----
    const int lrow = tid >> 2, lsl = tid & 3;              // 64 rows x 4 slots
    const uint32_t ld_off = swz(lrow, lsl);
    const char* gA = g_Xq + (size_t)(tok0 + lrow) * K_DIM + lsl * 16;
    const char* gB = g_Wq + (size_t)(out0 + lrow) * K_DIM + lsl * 16;

    // ---- ldmatrix per-thread offsets ----
    uint32_t offA[4][2], offB[2][2];
#pragma unroll
    for (int mt = 0; mt < 4; mt++) {
        int row = warpRow * 64 + mt * 16 + (lid & 15);
#pragma unroll
        for (int ks = 0; ks < 2; ks++)
            offA[mt][ks] = swz(row, ks * 2 + (lid >> 4));
    }
#pragma unroll
    for (int p = 0; p < 2; p++) {
        int row = warpCol * 32 + p * 16 + (lid & 15);
#pragma unroll
        for (int ks = 0; ks < 2; ks++)
            offB[p][ks] = swz(row, ks * 2 + (lid >> 4));
    }

    int acc[4][4][4];
#pragma unroll
    for (int mt = 0; mt < 4; mt++)
#pragma unroll
        for (int nt = 0; nt < 4; nt++)
#pragma unroll
            for (int r = 0; r < 4; r++) acc[mt][nt][r] = 0;

    // ---- prefetch chunk pairs {0,1} and {2,3} as two commit groups ----
#pragma unroll
    for (int g = 0; g < 2; g++) {
#pragma unroll
        for (int u = 0; u < 2; u++) {
            int cc = g * 2 + u;
            uint32_t sA = sm + cc * STAGE_BYTES;
            uint32_t sB = sA + BM * BK;
            size_t gofs = (size_t)cc * BK;
            CP16(sA + ld_off,        gA + gofs);
            CP16(sA + ld_off + 4096, gA + gofs + (size_t)64 * K_DIM);
            CP16(sB + ld_off,        gB + gofs);
            CP16(sB + ld_off + 4096, gB + gofs + (size_t)64 * K_DIM);
        }
        CP_COMMIT();
    }

    // ---- main loop: one barrier per 2 chunks ----
    int rd = 0, wr = 4;                                    // ring slots (mod 6)
#pragma unroll 1
    for (int i = 0; i < NPAIR; i++) {
        if (i + 2 < NPAIR) { CP_WAIT1(); } else { CP_WAIT0(); }
        __syncthreads();
        int cpre = 2 * i + 4;
        if (cpre < NCHUNK) {
#pragma unroll
            for (int u = 0; u < 2; u++) {
                uint32_t sA = sm + (wr + u) * STAGE_BYTES;
                uint32_t sB = sA + BM * BK;
                size_t gofs = (size_t)(cpre + u) * BK;
                CP16(sA + ld_off,        gA + gofs);
                CP16(sA + ld_off + 4096, gA + gofs + (size_t)64 * K_DIM);
                CP16(sB + ld_off,        gB + gofs);
                CP16(sB + ld_off + 4096, gB + gofs + (size_t)64 * K_DIM);
            }
            CP_COMMIT();
            wr += 2; if (wr == NSTAGE) wr = 0;
        }

#pragma unroll
        for (int u = 0; u < 2; u++) {
            uint32_t sA = sm + (rd + u) * STAGE_BYTES;
            uint32_t sB = sA + BM * BK;
#pragma unroll
            for (int ks = 0; ks < 2; ks++) {
                uint32_t a[4][4], b[2][4];
#pragma unroll
                for (int mt = 0; mt < 4; mt++)
                    ldsm4(a[mt][0], a[mt][1], a[mt][2], a[mt][3], sA + offA[mt][ks]);
#pragma unroll
                for (int p = 0; p < 2; p++)
                    ldsm4(b[p][0], b[p][1], b[p][2], b[p][3], sB + offB[p][ks]);
#pragma unroll
                for (int mt = 0; mt < 4; mt++)
#pragma unroll
                    for (int nt = 0; nt < 4; nt++) {
                        int p = nt >> 1, od = nt & 1;
                        MMA_S8(acc[mt][nt], a[mt], b[p][od], b[p][2 + od]);
                    }
            }
        }
        rd += 2; if (rd == NSTAGE) rd = 0;
    }

    // ---- epilogue: Y = cs*rs*(acc - zp*wsum) + b ----
    const int tq = lid >> 2, tr = lid & 3;
#pragma unroll
    for (int mt = 0; mt < 4; mt++) {
#pragma unroll
        for (int sub = 0; sub < 2; sub++) {
            int rr = warpRow * 64 + mt * 16 + tq + sub * 8;   // local token row
            float cs = s_cs[rr];
            int izp = s_zpi[rr];
            float* orow = out + (size_t)(tok0 + rr) * M_DIM + out0;
#pragma unroll
            for (int nt = 0; nt < 4; nt++) {
                int cc = warpCol * 32 + nt * 8 + tr * 2;      // local feature col
                int a0 = acc[mt][nt][sub * 2 + 0];
                int a1 = acc[mt][nt][sub * 2 + 1];
                float2 y;
                y.x = cs * s_rs[cc]     * (float)(a0 - izp * s_wsi[cc])     + s_b[cc];
                y.y = cs * s_rs[cc + 1] * (float)(a1 - izp * s_wsi[cc + 1]) + s_b[cc + 1];
                *(float2*)(orow + cc) = y;
            }
        }
    }
}

// ---------------- launch ----------------
extern "C" void kernel_launch(void* const* d_in, const int* in_sizes, int n_in,
                              void* d_out, int out_size) {
    const float* x = (const float*)d_in[0];
    const float* W = (const float*)d_in[1];
    const float* b = (const float*)d_in[2];
    float* out = (float*)d_out;

    int n_tok = in_sizes[0] / K_DIM;        // 8192
    int tokTiles = n_tok / BM;              // 64

    quant_kernel<<<M_DIM + n_tok, 256>>>(W, x);

    cudaFuncSetAttribute(gemm_kernel, cudaFuncAttributeMaxDynamicSharedMemorySize, GEMM_SMEM);
    dim3 grid(M_DIM / BN, tokTiles);        // (32, 64)
    gemm_kernel<<<grid, 256, GEMM_SMEM>>>(b, out);

    (void)n_in; (void)out_size;
}

// round 12
// speedup vs baseline: 1.0210x; 1.0210x over previous
#include <cuda_runtime.h>
#include <cuda_bf16.h>
#include <cstdint>
#include <cfloat>

#define K_DIM 4096
#define M_DIM 4096
#define NTOK_MAX 8192

// ---------------- scratch (device globals; no allocation allowed) ----------------
__device__ __align__(256) char g_Xq[(size_t)NTOK_MAX * K_DIM]; // int8 Xq (zp-offset included)
__device__ __align__(256) char g_Wq[(size_t)M_DIM * K_DIM];    // int8 Wq
__device__ float g_cs[NTOK_MAX];   // per-token act scale
__device__ float g_zp[NTOK_MAX];   // per-token zero point (integer-valued)
__device__ float g_rs[M_DIM];      // per-row weight scale
__device__ int   g_ws[M_DIM];      // per-row sum of Wq (int)

// ---------------- helpers ----------------
__device__ __forceinline__ uint32_t smem_u32(const void* p) {
    uint32_t a;
    asm("{ .reg .u64 t; cvta.to.shared.u64 t, %1; cvt.u32.u64 %0, t; }" : "=r"(a) : "l"(p));
    return a;
}
#define CP16(sm, gm) \
    asm volatile("cp.async.cg.shared.global [%0], [%1], 16;" :: "r"(sm), "l"(gm) : "memory")
#define CP_COMMIT() asm volatile("cp.async.commit_group;" ::: "memory")
#define CP_WAIT2()  asm volatile("cp.async.wait_group 2;" ::: "memory")

__device__ __forceinline__ void ldsm4(uint32_t& r0, uint32_t& r1, uint32_t& r2, uint32_t& r3,
                                      uint32_t addr) {
    asm volatile("ldmatrix.sync.aligned.m8n8.x4.shared.b16 {%0,%1,%2,%3}, [%4];"
                 : "=r"(r0), "=r"(r1), "=r"(r2), "=r"(r3) : "r"(addr));
}
#define MMA_S8(d, a, b0, b1) \
    asm volatile("mma.sync.aligned.m16n8k32.row.col.s32.s8.s8.s32 " \
                 "{%0,%1,%2,%3}, {%4,%5,%6,%7}, {%8,%9}, {%0,%1,%2,%3};" \
                 : "+r"((d)[0]), "+r"((d)[1]), "+r"((d)[2]), "+r"((d)[3]) \
                 : "r"((a)[0]), "r"((a)[1]), "r"((a)[2]), "r"((a)[3]), "r"(b0), "r"(b1))

// ---------------- fused quantization: one row per 256-thread block ----------------
// Blocks [0, M_DIM): weight rows (symmetric int8 + row sum).
// Blocks [M_DIM, M_DIM + n_tok): activation tokens (asymmetric int8).
// Single pass over data: values cached in 4 x float4 registers per thread.
__global__ __launch_bounds__(256) void quant_kernel(const float* __restrict__ W,
                                                    const float* __restrict__ X) {
    const int t = threadIdx.x;
    __shared__ float sr0[8], sr1[8];
    __shared__ int sqs[8];
    __shared__ float s_scale, s_zp;

    if (blockIdx.x < M_DIM) {
        // ---- weight row: symmetric ----
        const int m = blockIdx.x;
        const float4* row = reinterpret_cast<const float4*>(W + (size_t)m * K_DIM);
        float4 v[4];
        float amax = 0.f;
#pragma unroll
        for (int i = 0; i < 4; i++) {
            v[i] = row[t + i * 256];
            amax = fmaxf(amax, fmaxf(fmaxf(fabsf(v[i].x), fabsf(v[i].y)),
                                     fmaxf(fabsf(v[i].z), fabsf(v[i].w))));
        }
#pragma unroll
        for (int o = 16; o; o >>= 1) amax = fmaxf(amax, __shfl_xor_sync(0xFFFFFFFFu, amax, o));
        if ((t & 31) == 0) sr0[t >> 5] = amax;
        __syncthreads();
        if (t == 0) {
            float a = sr0[0];
#pragma unroll
            for (int i = 1; i < 8; i++) a = fmaxf(a, sr0[i]);
            float sc = (a > 0.f) ? __fdiv_rn(a, 127.f) : 1.f;
            s_scale = sc;
            g_rs[m] = sc;
        }
        __syncthreads();
        const float sc = s_scale;
        uint32_t* o = reinterpret_cast<uint32_t*>(g_Wq + (size_t)m * K_DIM);
        int qsum = 0;
#pragma unroll
        for (int i = 0; i < 4; i++) {
            int i0 = (int)fminf(fmaxf(rintf(__fdiv_rn(v[i].x, sc)), -128.f), 127.f);
            int i1 = (int)fminf(fmaxf(rintf(__fdiv_rn(v[i].y, sc)), -128.f), 127.f);
            int i2 = (int)fminf(fmaxf(rintf(__fdiv_rn(v[i].z, sc)), -128.f), 127.f);
            int i3 = (int)fminf(fmaxf(rintf(__fdiv_rn(v[i].w, sc)), -128.f), 127.f);
            qsum += i0 + i1 + i2 + i3;
            o[t + i * 256] = (uint32_t)(i0 & 255) | ((uint32_t)(i1 & 255) << 8) |
                             ((uint32_t)(i2 & 255) << 16) | ((uint32_t)(i3 & 255) << 24);
        }
#pragma unroll
        for (int ofs = 16; ofs; ofs >>= 1) qsum += __shfl_xor_sync(0xFFFFFFFFu, qsum, ofs);
        if ((t & 31) == 0) sqs[t >> 5] = qsum;
        __syncthreads();
        if (t == 0) {
            int s = 0;
#pragma unroll
            for (int i = 0; i < 8; i++) s += sqs[i];
            g_ws[m] = s;
        }
    } else {
        // ---- activation token: asymmetric ----
        const int n = blockIdx.x - M_DIM;
        const float4* row = reinterpret_cast<const float4*>(X + (size_t)n * K_DIM);
        float4 v[4];
        float mn = FLT_MAX, mx = -FLT_MAX;
#pragma unroll
        for (int i = 0; i < 4; i++) {
            v[i] = row[t + i * 256];
            mn = fminf(mn, fminf(fminf(v[i].x, v[i].y), fminf(v[i].z, v[i].w)));
            mx = fmaxf(mx, fmaxf(fmaxf(v[i].x, v[i].y), fmaxf(v[i].z, v[i].w)));
        }
#pragma unroll
        for (int o = 16; o; o >>= 1) {
            mn = fminf(mn, __shfl_xor_sync(0xFFFFFFFFu, mn, o));
            mx = fmaxf(mx, __shfl_xor_sync(0xFFFFFFFFu, mx, o));
        }
        if ((t & 31) == 0) { sr0[t >> 5] = mn; sr1[t >> 5] = mx; }
        __syncthreads();
        if (t == 0) {
            float lo = sr0[0], hi = sr1[0];
#pragma unroll
            for (int i = 1; i < 8; i++) {
                lo = fminf(lo, sr0[i]);
                hi = fmaxf(hi, sr1[i]);
            }
            float rng = hi - lo;
            float sc = (rng > 0.f) ? __fdiv_rn(rng, 255.f) : 1.f;
            float zp = fminf(fmaxf(rintf(-128.f - __fdiv_rn(lo, sc)), -128.f), 127.f);
            s_scale = sc; s_zp = zp;
            g_cs[n] = sc;
            g_zp[n] = zp;
        }
        __syncthreads();
        const float sc = s_scale, zp = s_zp;
        uint32_t* o = reinterpret_cast<uint32_t*>(g_Xq + (size_t)n * K_DIM);
#pragma unroll
        for (int i = 0; i < 4; i++) {
            int i0 = (int)(fminf(fmaxf(rintf(__fdiv_rn(v[i].x, sc) + zp), -128.f), 127.f));
            int i1 = (int)(fminf(fmaxf(rintf(__fdiv_rn(v[i].y, sc) + zp), -128.f), 127.f));
            int i2 = (int)(fminf(fmaxf(rintf(__fdiv_rn(v[i].z, sc) + zp), -128.f), 127.f));
            int i3 = (int)(fminf(fmaxf(rintf(__fdiv_rn(v[i].w, sc) + zp), -128.f), 127.f));
            o[t + i * 256] = (uint32_t)(i0 & 255) | ((uint32_t)(i1 & 255) << 8) |
                             ((uint32_t)(i2 & 255) << 16) | ((uint32_t)(i3 & 255) << 24);
        }
    }
}

// ---------------- int8 IMMA GEMM (R5/R10 champion config) ----------------
// CTA tile: 128 tokens x 128 features, BK = 64 B, 4-stage cp.async pipeline.
// 8 warps in 2x4; warp tile 64x32. 2 CTAs/SM (smem 68KB, regs <=128).
// Change vs R10: first prefetch commit issued BEFORE ctrl-constant LDGs.
#define BM 128
#define BN 128
#define BK 64
#define NSTAGE 4
#define NCHUNK (K_DIM / BK)                // 64
#define STAGE_BYTES ((BM + BN) * BK)       // 16384
#define CTRL_OFF (NSTAGE * STAGE_BYTES)    // 65536
#define GEMM_SMEM (CTRL_OFF + 2560)        // 68096

// swizzled offset of a 16B slot within a [rows x 64B] tile
__device__ __forceinline__ uint32_t swz(int row, int slot) {
    return (uint32_t)(row * 64 + ((slot ^ ((row >> 1) & 3)) << 4));
}

__global__ void __launch_bounds__(256, 2) gemm_kernel(const float* __restrict__ bias,
                                                      float* __restrict__ out) {
    extern __shared__ char smem[];
    uint32_t sm = smem_u32(smem);
    const int tid = threadIdx.x;
    const int wid = tid >> 5, lid = tid & 31;
    const int warpRow = wid >> 2, warpCol = wid & 3;       // 2 x 4 warps
    const int outTile = blockIdx.x;                        // 32 tiles of 128 features
    const int tokTile = blockIdx.y;                        // 64 tiles of 128 tokens
    const int tok0 = tokTile * BM, out0 = outTile * BN;

    // ---- loader per-thread invariants ----
    const int lrow = tid >> 2, lsl = tid & 3;              // 64 rows x 4 slots
    const uint32_t ld_off = swz(lrow, lsl);
    const char* gA = g_Xq + (size_t)(tok0 + lrow) * K_DIM + lsl * 16;
    const char* gB = g_Wq + (size_t)(out0 + lrow) * K_DIM + lsl * 16;

    // ---- prefetch stages 0..2 FIRST (gets cp.async stream going ASAP) ----
#pragma unroll
    for (int s = 0; s < NSTAGE - 1; s++) {
        uint32_t sA = sm + s * STAGE_BYTES;
        uint32_t sB = sA + BM * BK;
        size_t gofs = (size_t)s * BK;
        CP16(sA + ld_off,        gA + gofs);
        CP16(sA + ld_off + 4096, gA + gofs + (size_t)64 * K_DIM);
        CP16(sB + ld_off,        gB + gofs);
        CP16(sB + ld_off + 4096, gB + gofs + (size_t)64 * K_DIM);
        CP_COMMIT();
    }

    // ---- ctrl smem (epilogue constants) — off the critical path ----
    float* s_cs  = (float*)(smem + CTRL_OFF);          // 128 floats
    int*   s_zpi = (int*)(smem + CTRL_OFF + 512);      // 128 ints
    float* s_rs  = (float*)(smem + CTRL_OFF + 1024);   // 128 floats
    int*   s_wsi = (int*)(smem + CTRL_OFF + 1536);     // 128 ints
    float* s_b   = (float*)(smem + CTRL_OFF + 2048);   // 128 floats
    if (tid < 128) {
        s_cs[tid]  = g_cs[tok0 + tid];
        s_zpi[tid] = (int)g_zp[tok0 + tid];
        s_rs[tid]  = g_rs[out0 + tid];
        s_wsi[tid] = g_ws[out0 + tid];
        s_b[tid]   = bias[out0 + tid];
    }

    // ---- ldmatrix per-thread offsets ----
    uint32_t offA[4][2], offB[2][2];
#pragma unroll
    for (int mt = 0; mt < 4; mt++) {
        int row = warpRow * 64 + mt * 16 + (lid & 15);
#pragma unroll
        for (int ks = 0; ks < 2; ks++)
            offA[mt][ks] = swz(row, ks * 2 + (lid >> 4));
    }
#pragma unroll
    for (int p = 0; p < 2; p++) {
        int row = warpCol * 32 + p * 16 + (lid & 15);
#pragma unroll
        for (int ks = 0; ks < 2; ks++)
            offB[p][ks] = swz(row, ks * 2 + (lid >> 4));
    }

    int acc[4][4][4];
#pragma unroll
    for (int mt = 0; mt < 4; mt++)
#pragma unroll
        for (int nt = 0; nt < 4; nt++)
#pragma unroll
            for (int r = 0; r < 4; r++) acc[mt][nt][r] = 0;

    // ---- main loop ----
#pragma unroll 1
    for (int c = 0; c < NCHUNK; c++) {
        CP_WAIT2();
        __syncthreads();
        if (c + NSTAGE - 1 < NCHUNK) {
            int s = (c + NSTAGE - 1) & (NSTAGE - 1);
            uint32_t sA = sm + s * STAGE_BYTES;
            uint32_t sB = sA + BM * BK;
            size_t gofs = (size_t)(c + NSTAGE - 1) * BK;
            CP16(sA + ld_off,        gA + gofs);
            CP16(sA + ld_off + 4096, gA + gofs + (size_t)64 * K_DIM);
            CP16(sB + ld_off,        gB + gofs);
            CP16(sB + ld_off + 4096, gB + gofs + (size_t)64 * K_DIM);
        }
        CP_COMMIT();

        uint32_t sA = sm + (c & (NSTAGE - 1)) * STAGE_BYTES;
        uint32_t sB = sA + BM * BK;
#pragma unroll
        for (int ks = 0; ks < 2; ks++) {
            uint32_t a[4][4], b[2][4];
#pragma unroll
            for (int mt = 0; mt < 4; mt++)
                ldsm4(a[mt][0], a[mt][1], a[mt][2], a[mt][3], sA + offA[mt][ks]);
#pragma unroll
            for (int p = 0; p < 2; p++)
                ldsm4(b[p][0], b[p][1], b[p][2], b[p][3], sB + offB[p][ks]);
#pragma unroll
            for (int mt = 0; mt < 4; mt++)
#pragma unroll
                for (int nt = 0; nt < 4; nt++) {
                    int p = nt >> 1, od = nt & 1;
                    MMA_S8(acc[mt][nt], a[mt], b[p][od], b[p][2 + od]);
                }
        }
    }

    // ---- epilogue: Y = cs*rs*(acc - zp*wsum) + b ----
    const int tq = lid >> 2, tr = lid & 3;
#pragma unroll
    for (int mt = 0; mt < 4; mt++) {
#pragma unroll
        for (int sub = 0; sub < 2; sub++) {
            int rr = warpRow * 64 + mt * 16 + tq + sub * 8;   // local token row
            float cs = s_cs[rr];
            int izp = s_zpi[rr];
            float* orow = out + (size_t)(tok0 + rr) * M_DIM + out0;
#pragma unroll
            for (int nt = 0; nt < 4; nt++) {
                int cc = warpCol * 32 + nt * 8 + tr * 2;      // local feature col
                int a0 = acc[mt][nt][sub * 2 + 0];
                int a1 = acc[mt][nt][sub * 2 + 1];
                float2 y;
                y.x = cs * s_rs[cc]     * (float)(a0 - izp * s_wsi[cc])     + s_b[cc];
                y.y = cs * s_rs[cc + 1] * (float)(a1 - izp * s_wsi[cc + 1]) + s_b[cc + 1];
                *(float2*)(orow + cc) = y;
            }
        }
    }
}

// ---------------- launch ----------------
extern "C" void kernel_launch(void* const* d_in, const int* in_sizes, int n_in,
                              void* d_out, int out_size) {
    const float* x = (const float*)d_in[0];
    const float* W = (const float*)d_in[1];
    const float* b = (const float*)d_in[2];
    float* out = (float*)d_out;

    int n_tok = in_sizes[0] / K_DIM;        // 8192
    int tokTiles = n_tok / BM;              // 64

    quant_kernel<<<M_DIM + n_tok, 256>>>(W, x);

    cudaFuncSetAttribute(gemm_kernel, cudaFuncAttributeMaxDynamicSharedMemorySize, GEMM_SMEM);
    dim3 grid(M_DIM / BN, tokTiles);        // (32, 64)
    gemm_kernel<<<grid, 256, GEMM_SMEM>>>(b, out);

    (void)n_in; (void)out_size;
}